// round 3
// baseline (speedup 1.0000x reference)
#include <cuda_runtime.h>
#include <cuda_bf16.h>

#define MAXN 50000
#define MAXE 800000
#define CH   64
#define NG   64

// ---------------- scratch (device globals: no runtime allocation) ----------
__device__ __align__(16) float g_deg[MAXN];
__device__ __align__(16) float g_dinv[MAXN];
__device__ __align__(16) float g_selfnorm[MAXN];
__device__ __align__(16) float g_norm[MAXE];
__device__ __align__(16) float g_hraw[MAXN * CH];
__device__ __align__(16) float g_acc [MAXN * CH];
__device__ __align__(16) float g_skip[MAXN * CH];
__device__ __align__(16) float g_h   [MAXN * CH];
__device__ __align__(16) float g_pooled[NG * CH];
__device__ __align__(16) float g_cnt[NG];

// ---------------- kernels --------------------------------------------------

__global__ void k_init(int n) {
    int i = blockIdx.x * blockDim.x + threadIdx.x;
    if (i < n)       g_deg[i] = 1.0f;
    if (i < NG * CH) g_pooled[i] = 0.0f;
    if (i < NG)      g_cnt[i] = 0.0f;
}

__global__ void k_deg(const int* __restrict__ dst, int nE) {
    int e = blockIdx.x * blockDim.x + threadIdx.x;
    if (e < nE) atomicAdd(&g_deg[dst[e]], 1.0f);
}

__global__ void k_dinv(int n) {
    int i = blockIdx.x * blockDim.x + threadIdx.x;
    if (i < n) {
        float r = rsqrtf(g_deg[i]);
        g_dinv[i] = r;
        g_selfnorm[i] = r * r;
    }
}

__global__ void k_norm(const int* __restrict__ src, const int* __restrict__ dst, int nE) {
    int e = blockIdx.x * blockDim.x + threadIdx.x;
    if (e < nE) g_norm[e] = g_dinv[src[e]] * g_dinv[dst[e]];
}

// GEMM: X[n,64] @ W[64,64]. 64x64 tile per block, 256 threads, 4x4 reg tile.
// mode 0: OUT_H = X@W ; OUT_ACC = selfnorm * (X@W) + b   (GCN pre-scatter)
// mode 1: OUT_ACC = relu(X@W + b)                        (dense skip)
__global__ void k_gemm(const float* __restrict__ X, const float* __restrict__ W,
                       const float* __restrict__ b, int n, int mode,
                       float* __restrict__ OUT_H, float* __restrict__ OUT_ACC)
{
    __shared__ __align__(16) float Ws[64 * 64];
    __shared__ __align__(16) float Xs[64 * 65];  // padded to kill bank conflicts

    int tid = threadIdx.x;
    int row0 = blockIdx.x * 64;

    // load W (4096 floats) with float4
    {
        const float4* W4 = (const float4*)W;
        float4* Ws4 = (float4*)Ws;
        for (int i = tid; i < 1024; i += 256) Ws4[i] = W4[i];
    }
    // load X tile (64 rows x 64 cols), zero-pad OOB rows
    for (int i = tid; i < 1024; i += 256) {
        int r  = i >> 4;           // 0..63
        int c4 = (i & 15) << 2;    // 0,4,...,60
        int gr = row0 + r;
        float4 v = make_float4(0.f, 0.f, 0.f, 0.f);
        if (gr < n) v = *(const float4*)(X + gr * 64 + c4);
        float* p = &Xs[r * 65 + c4];
        p[0] = v.x; p[1] = v.y; p[2] = v.z; p[3] = v.w;
    }
    __syncthreads();

    int tx = tid & 15;   // col group (4 cols)
    int ty = tid >> 4;   // row group (4 rows)

    float acc00=0,acc01=0,acc02=0,acc03=0;
    float acc10=0,acc11=0,acc12=0,acc13=0;
    float acc20=0,acc21=0,acc22=0,acc23=0;
    float acc30=0,acc31=0,acc32=0,acc33=0;

    #pragma unroll
    for (int k = 0; k < 64; k++) {
        float4 w = *(const float4*)&Ws[k * 64 + tx * 4];
        float a0 = Xs[(ty * 4 + 0) * 65 + k];
        float a1 = Xs[(ty * 4 + 1) * 65 + k];
        float a2 = Xs[(ty * 4 + 2) * 65 + k];
        float a3 = Xs[(ty * 4 + 3) * 65 + k];
        acc00 = fmaf(a0, w.x, acc00); acc01 = fmaf(a0, w.y, acc01);
        acc02 = fmaf(a0, w.z, acc02); acc03 = fmaf(a0, w.w, acc03);
        acc10 = fmaf(a1, w.x, acc10); acc11 = fmaf(a1, w.y, acc11);
        acc12 = fmaf(a1, w.z, acc12); acc13 = fmaf(a1, w.w, acc13);
        acc20 = fmaf(a2, w.x, acc20); acc21 = fmaf(a2, w.y, acc21);
        acc22 = fmaf(a2, w.z, acc22); acc23 = fmaf(a2, w.w, acc23);
        acc30 = fmaf(a3, w.x, acc30); acc31 = fmaf(a3, w.y, acc31);
        acc32 = fmaf(a3, w.z, acc32); acc33 = fmaf(a3, w.w, acc33);
    }

    int c0 = tx * 4;
    float4 bv = *(const float4*)(b + c0);

    float rows[4][4] = {{acc00,acc01,acc02,acc03},
                        {acc10,acc11,acc12,acc13},
                        {acc20,acc21,acc22,acc23},
                        {acc30,acc31,acc32,acc33}};
    #pragma unroll
    for (int i = 0; i < 4; i++) {
        int r = row0 + ty * 4 + i;
        if (r >= n) break;
        float4 v = make_float4(rows[i][0], rows[i][1], rows[i][2], rows[i][3]);
        if (mode == 0) {
            *(float4*)(OUT_H + r * 64 + c0) = v;
            float sn = g_selfnorm[r];
            float4 a = make_float4(fmaf(sn, v.x, bv.x), fmaf(sn, v.y, bv.y),
                                   fmaf(sn, v.z, bv.z), fmaf(sn, v.w, bv.w));
            *(float4*)(OUT_ACC + r * 64 + c0) = a;
        } else {
            float4 a = make_float4(fmaxf(v.x + bv.x, 0.f), fmaxf(v.y + bv.y, 0.f),
                                   fmaxf(v.z + bv.z, 0.f), fmaxf(v.w + bv.w, 0.f));
            *(float4*)(OUT_ACC + r * 64 + c0) = a;
        }
    }
}

// scatter: ACC[dst] += norm[e] * H[src]   (16 threads per edge, float4 red)
__global__ void k_scatter(const float* __restrict__ H, float* __restrict__ ACC,
                          const int* __restrict__ src, const int* __restrict__ dst,
                          int nE)
{
    int t = blockIdx.x * blockDim.x + threadIdx.x;
    int e = t >> 4;
    if (e >= nE) return;
    int c4 = (t & 15) << 2;
    int s = src[e], d = dst[e];
    float w = g_norm[e];
    float4 hv = *(const float4*)(H + s * 64 + c4);
    float* p = ACC + d * 64 + c4;
    asm volatile("red.global.add.v4.f32 [%0], {%1,%2,%3,%4};"
                 :: "l"(p), "f"(hv.x * w), "f"(hv.y * w), "f"(hv.z * w), "f"(hv.w * w)
                 : "memory");
}

// OUT = relu(ACC) + SKIP, float4 (in-place safe when OUT==SKIP)
__global__ void k_post(const float* __restrict__ ACC, const float* __restrict__ SKIP,
                       float* __restrict__ OUT, int n4)
{
    int i = blockIdx.x * blockDim.x + threadIdx.x;
    if (i >= n4) return;
    float4 a = *(const float4*)(ACC + i * 4);
    float4 s = *(const float4*)(SKIP + i * 4);
    float4 o = make_float4(fmaxf(a.x, 0.f) + s.x, fmaxf(a.y, 0.f) + s.y,
                           fmaxf(a.z, 0.f) + s.z, fmaxf(a.w, 0.f) + s.w);
    *(float4*)(OUT + i * 4) = o;
}

// pool: g_pooled[batch[node]] += H[node]  (16 threads per node, float4 red)
__global__ void k_pool(const float* __restrict__ H, const int* __restrict__ batch, int n)
{
    int t = blockIdx.x * blockDim.x + threadIdx.x;
    int node = t >> 4;
    if (node >= n) return;
    int c4 = (t & 15) << 2;
    int g = batch[node];
    float4 v = *(const float4*)(H + node * 64 + c4);
    float* p = g_pooled + g * 64 + c4;
    asm volatile("red.global.add.v4.f32 [%0], {%1,%2,%3,%4};"
                 :: "l"(p), "f"(v.x), "f"(v.y), "f"(v.z), "f"(v.w)
                 : "memory");
}

__global__ void k_cnt(const int* __restrict__ batch, int n) {
    int i = blockIdx.x * blockDim.x + threadIdx.x;
    if (i < n) atomicAdd(&g_cnt[batch[i]], 1.0f);
}

// out[g] = (sum_c pooled[g][c] * Wf[c]) / max(cnt,1) + bf
__global__ void k_final(const float* __restrict__ Wf, const float* __restrict__ bf,
                        float* __restrict__ out)
{
    int g = threadIdx.x;
    if (g >= NG) return;
    float cnt = fmaxf(g_cnt[g], 1.0f);
    float acc = 0.f;
    #pragma unroll
    for (int c = 0; c < CH; c++) acc += g_pooled[g * CH + c] * Wf[c];
    out[g] = acc / cnt + bf[0];
}

// ---------------- host -----------------------------------------------------

extern "C" void kernel_launch(void* const* d_in, const int* in_sizes, int n_in,
                              void* d_out, int out_size)
{
    const float* x   = (const float*)d_in[0];
    const float* xsc = (const float*)d_in[1];
    const float* W1  = (const float*)d_in[2];
    const float* b1  = (const float*)d_in[3];
    const float* W2  = (const float*)d_in[4];
    const float* b2  = (const float*)d_in[5];
    const float* We  = (const float*)d_in[6];
    const float* be  = (const float*)d_in[7];
    const float* W1s = (const float*)d_in[8];
    const float* b1s = (const float*)d_in[9];
    const float* W2s = (const float*)d_in[10];
    const float* b2s = (const float*)d_in[11];
    const float* Wes = (const float*)d_in[12];
    const float* bes = (const float*)d_in[13];
    const float* Wf  = (const float*)d_in[14];
    const float* bf  = (const float*)d_in[15];
    const int*   ei  = (const int*)d_in[16];
    const int*   bat = (const int*)d_in[17];

    int n  = in_sizes[0] / CH;
    int nE = in_sizes[16] / 2;
    const int* src = ei;
    const int* dst = ei + nE;
    float* out = (float*)d_out;

    float *hraw, *acc, *skip, *h;
    cudaGetSymbolAddress((void**)&hraw, g_hraw);
    cudaGetSymbolAddress((void**)&acc,  g_acc);
    cudaGetSymbolAddress((void**)&skip, g_skip);
    cudaGetSymbolAddress((void**)&h,    g_h);

    const int T = 256;
    int gN   = (n + T - 1) / T;
    int gE   = (nE + T - 1) / T;
    int gTile = (n + 63) / 64;
    int gE16 = (nE * 16 + T - 1) / T;   // scatter
    int gN16 = (n * 16 + T - 1) / T;    // pool / post (n*64/4 = n*16 float4)

    k_init<<<gN, T>>>(n);
    k_deg<<<gE, T>>>(dst, nE);
    k_dinv<<<gN, T>>>(n);
    k_norm<<<gE, T>>>(src, dst, nE);

    // ---- branch 1: x with W1/We/W2 ----
    k_gemm<<<gTile, T>>>(x, W1, b1, n, 0, hraw, acc);
    k_gemm<<<gTile, T>>>(x, We, be, n, 1, nullptr, skip);
    k_scatter<<<gE16, T>>>(hraw, acc, src, dst, nE);
    k_post<<<gN16, T>>>(acc, skip, h, n * 16);
    k_gemm<<<gTile, T>>>(h, W2, b2, n, 0, hraw, acc);
    k_scatter<<<gE16, T>>>(hraw, acc, src, dst, nE);
    k_post<<<gN16, T>>>(acc, h, h, n * 16);
    k_pool<<<gN16, T>>>(h, bat, n);

    // ---- branch 2: x_SC with W1s/Wes/W2s ----
    k_gemm<<<gTile, T>>>(xsc, W1s, b1s, n, 0, hraw, acc);
    k_gemm<<<gTile, T>>>(xsc, Wes, bes, n, 1, nullptr, skip);
    k_scatter<<<gE16, T>>>(hraw, acc, src, dst, nE);
    k_post<<<gN16, T>>>(acc, skip, h, n * 16);
    k_gemm<<<gTile, T>>>(h, W2s, b2s, n, 0, hraw, acc);
    k_scatter<<<gE16, T>>>(hraw, acc, src, dst, nE);
    k_post<<<gN16, T>>>(acc, h, h, n * 16);
    k_pool<<<gN16, T>>>(h, bat, n);

    k_cnt<<<gN, T>>>(bat, n);
    k_final<<<1, 64>>>(Wf, bf, out);
}

// round 4
// speedup vs baseline: 1.1045x; 1.1045x over previous
#include <cuda_runtime.h>
#include <cuda_bf16.h>

#define MAXN 50000
#define MAXE 800000
#define CH   64
#define NG   64

// ---------------- scratch (device globals: no runtime allocation) ----------
__device__ __align__(16) float g_dinv[MAXN];
__device__ __align__(16) float g_selfnorm[MAXN];
__device__ __align__(16) int   g_cnt_i[MAXN];
__device__ __align__(16) int   g_rowptr[MAXN + 1];
__device__ __align__(16) int   g_cursor[MAXN];
__device__ __align__(16) int2  g_cedge[MAXE];      // {src, w-as-int-bits}
__device__ __align__(16) float g_hraw[MAXN * CH];
__device__ __align__(16) float g_skip[MAXN * CH];
__device__ __align__(16) float g_h   [MAXN * CH];
__device__ __align__(16) float g_pooled[NG * CH];
__device__ __align__(16) float g_cntf[NG];

// ---------------- build CSR ------------------------------------------------

__global__ void k_zero(int n) {
    int i = blockIdx.x * blockDim.x + threadIdx.x;
    if (i < n)       g_cnt_i[i] = 0;
    if (i < NG * CH) g_pooled[i] = 0.0f;
    if (i < NG)      g_cntf[i] = 0.0f;
}

__global__ void k_hist(const int* __restrict__ dst, int nE) {
    int e = blockIdx.x * blockDim.x + threadIdx.x;
    if (e < nE) atomicAdd(&g_cnt_i[dst[e]], 1);
}

__global__ void k_dinv(int n) {
    int i = blockIdx.x * blockDim.x + threadIdx.x;
    if (i < n) {
        float r = rsqrtf((float)g_cnt_i[i] + 1.0f);   // deg incl. self-loop
        g_dinv[i] = r;
        g_selfnorm[i] = r * r;
    }
}

// single-block exclusive scan of g_cnt_i -> g_rowptr / g_cursor
__global__ void k_scan(int n) {
    __shared__ int ssum[1024];
    int t = threadIdx.x;
    int chunk = (n + 1023) / 1024;
    int lo = t * chunk;
    int hi = min(lo + chunk, n);
    int s = 0;
    for (int i = lo; i < hi; i++) s += g_cnt_i[i];
    ssum[t] = s;
    __syncthreads();
    // Hillis-Steele inclusive scan
    for (int off = 1; off < 1024; off <<= 1) {
        int v = (t >= off) ? ssum[t - off] : 0;
        __syncthreads();
        ssum[t] += v;
        __syncthreads();
    }
    int run = (t == 0) ? 0 : ssum[t - 1];
    for (int i = lo; i < hi; i++) {
        int c = g_cnt_i[i];
        g_rowptr[i] = run;
        g_cursor[i] = run;
        run += c;
    }
    if (t == 1023) g_rowptr[n] = ssum[1023];
}

__global__ void k_place(const int* __restrict__ src, const int* __restrict__ dst, int nE) {
    int e = blockIdx.x * blockDim.x + threadIdx.x;
    if (e >= nE) return;
    int s = src[e], d = dst[e];
    int pos = atomicAdd(&g_cursor[d], 1);
    float w = g_dinv[s] * g_dinv[d];
    g_cedge[pos] = make_int2(s, __float_as_int(w));
}

// ---------------- GEMM: X[n,64] @ W[64,64] ---------------------------------
// mode 0: OUT = X@W                      (raw product, pre-aggregate)
// mode 1: OUT = relu(X@W + b)            (dense skip branch)
__global__ void k_gemm(const float* __restrict__ X, const float* __restrict__ W,
                       const float* __restrict__ b, int n, int mode,
                       float* __restrict__ OUT)
{
    __shared__ __align__(16) float Ws[64 * 64];
    __shared__ __align__(16) float Xs[64 * 65];  // padded

    int tid = threadIdx.x;
    int row0 = blockIdx.x * 64;

    {
        const float4* W4 = (const float4*)W;
        float4* Ws4 = (float4*)Ws;
        for (int i = tid; i < 1024; i += 256) Ws4[i] = W4[i];
    }
    for (int i = tid; i < 1024; i += 256) {
        int r  = i >> 4;
        int c4 = (i & 15) << 2;
        int gr = row0 + r;
        float4 v = make_float4(0.f, 0.f, 0.f, 0.f);
        if (gr < n) v = *(const float4*)(X + gr * 64 + c4);
        float* p = &Xs[r * 65 + c4];
        p[0] = v.x; p[1] = v.y; p[2] = v.z; p[3] = v.w;
    }
    __syncthreads();

    int tx = tid & 15;
    int ty = tid >> 4;

    float a00=0,a01=0,a02=0,a03=0, a10=0,a11=0,a12=0,a13=0;
    float a20=0,a21=0,a22=0,a23=0, a30=0,a31=0,a32=0,a33=0;

    #pragma unroll
    for (int k = 0; k < 64; k++) {
        float4 w = *(const float4*)&Ws[k * 64 + tx * 4];
        float x0 = Xs[(ty * 4 + 0) * 65 + k];
        float x1 = Xs[(ty * 4 + 1) * 65 + k];
        float x2 = Xs[(ty * 4 + 2) * 65 + k];
        float x3 = Xs[(ty * 4 + 3) * 65 + k];
        a00 = fmaf(x0, w.x, a00); a01 = fmaf(x0, w.y, a01);
        a02 = fmaf(x0, w.z, a02); a03 = fmaf(x0, w.w, a03);
        a10 = fmaf(x1, w.x, a10); a11 = fmaf(x1, w.y, a11);
        a12 = fmaf(x1, w.z, a12); a13 = fmaf(x1, w.w, a13);
        a20 = fmaf(x2, w.x, a20); a21 = fmaf(x2, w.y, a21);
        a22 = fmaf(x2, w.z, a22); a23 = fmaf(x2, w.w, a23);
        a30 = fmaf(x3, w.x, a30); a31 = fmaf(x3, w.y, a31);
        a32 = fmaf(x3, w.z, a32); a33 = fmaf(x3, w.w, a33);
    }

    int c0 = tx * 4;
    float4 bv = *(const float4*)(b + c0);

    float rows[4][4] = {{a00,a01,a02,a03},{a10,a11,a12,a13},
                        {a20,a21,a22,a23},{a30,a31,a32,a33}};
    #pragma unroll
    for (int i = 0; i < 4; i++) {
        int r = row0 + ty * 4 + i;
        if (r >= n) break;
        float4 v;
        if (mode == 0) {
            v = make_float4(rows[i][0], rows[i][1], rows[i][2], rows[i][3]);
        } else {
            v = make_float4(fmaxf(rows[i][0] + bv.x, 0.f), fmaxf(rows[i][1] + bv.y, 0.f),
                            fmaxf(rows[i][2] + bv.z, 0.f), fmaxf(rows[i][3] + bv.w, 0.f));
        }
        *(float4*)(OUT + r * 64 + c0) = v;
    }
}

// ---------------- fused GCN aggregate --------------------------------------
// OUT[d] = relu( sum_{e in CSR(d)} w_e * H[src_e] + selfnorm[d]*H[d] + b ) + SKIP[d]
// if DO_POOL: red-add OUT row into g_pooled[batch[d]]
// 16 threads per node, float4 per thread.
template<int DO_POOL>
__global__ void k_agg(const float* __restrict__ H, const float* __restrict__ SKIP,
                      float* __restrict__ OUT, const float* __restrict__ b,
                      const int* __restrict__ batch, int n)
{
    int t = blockIdx.x * blockDim.x + threadIdx.x;
    int node = t >> 4;
    if (node >= n) return;
    int c4 = (t & 15) << 2;

    int beg = g_rowptr[node];
    int end = g_rowptr[node + 1];

    float sn = g_selfnorm[node];
    float4 hd = *(const float4*)(H + node * 64 + c4);
    float4 acc = make_float4(sn * hd.x, sn * hd.y, sn * hd.z, sn * hd.w);

    for (int j = beg; j < end; j++) {
        int2 e = __ldg(&g_cedge[j]);            // broadcast across the 16-group
        float w = __int_as_float(e.y);
        float4 hv = *(const float4*)(H + e.x * 64 + c4);
        acc.x = fmaf(w, hv.x, acc.x);
        acc.y = fmaf(w, hv.y, acc.y);
        acc.z = fmaf(w, hv.z, acc.z);
        acc.w = fmaf(w, hv.w, acc.w);
    }

    float4 bv = *(const float4*)(b + c4);
    float4 sk = *(const float4*)(SKIP + node * 64 + c4);
    float4 o = make_float4(fmaxf(acc.x + bv.x, 0.f) + sk.x,
                           fmaxf(acc.y + bv.y, 0.f) + sk.y,
                           fmaxf(acc.z + bv.z, 0.f) + sk.z,
                           fmaxf(acc.w + bv.w, 0.f) + sk.w);
    *(float4*)(OUT + node * 64 + c4) = o;

    if (DO_POOL) {
        int g = batch[node];
        float* p = g_pooled + g * 64 + c4;
        asm volatile("red.global.add.v4.f32 [%0], {%1,%2,%3,%4};"
                     :: "l"(p), "f"(o.x), "f"(o.y), "f"(o.z), "f"(o.w)
                     : "memory");
    }
}

__global__ void k_cnt(const int* __restrict__ batch, int n) {
    int i = blockIdx.x * blockDim.x + threadIdx.x;
    if (i < n) atomicAdd(&g_cntf[batch[i]], 1.0f);
}

__global__ void k_final(const float* __restrict__ Wf, const float* __restrict__ bf,
                        float* __restrict__ out)
{
    int g = threadIdx.x;
    if (g >= NG) return;
    float cnt = fmaxf(g_cntf[g], 1.0f);
    float acc = 0.f;
    #pragma unroll
    for (int c = 0; c < CH; c++) acc += g_pooled[g * CH + c] * Wf[c];
    out[g] = acc / cnt + bf[0];
}

// ---------------- host -----------------------------------------------------

extern "C" void kernel_launch(void* const* d_in, const int* in_sizes, int n_in,
                              void* d_out, int out_size)
{
    const float* x   = (const float*)d_in[0];
    const float* xsc = (const float*)d_in[1];
    const float* W1  = (const float*)d_in[2];
    const float* b1  = (const float*)d_in[3];
    const float* W2  = (const float*)d_in[4];
    const float* b2  = (const float*)d_in[5];
    const float* We  = (const float*)d_in[6];
    const float* be  = (const float*)d_in[7];
    const float* W1s = (const float*)d_in[8];
    const float* b1s = (const float*)d_in[9];
    const float* W2s = (const float*)d_in[10];
    const float* b2s = (const float*)d_in[11];
    const float* Wes = (const float*)d_in[12];
    const float* bes = (const float*)d_in[13];
    const float* Wf  = (const float*)d_in[14];
    const float* bf  = (const float*)d_in[15];
    const int*   ei  = (const int*)d_in[16];
    const int*   bat = (const int*)d_in[17];

    int n  = in_sizes[0] / CH;
    int nE = in_sizes[16] / 2;
    const int* src = ei;
    const int* dst = ei + nE;
    float* out = (float*)d_out;

    float *hraw, *skip, *h;
    cudaGetSymbolAddress((void**)&hraw, g_hraw);
    cudaGetSymbolAddress((void**)&skip, g_skip);
    cudaGetSymbolAddress((void**)&h,    g_h);

    const int T = 256;
    int gN    = (n + T - 1) / T;
    int gE    = (nE + T - 1) / T;
    int gTile = (n + 63) / 64;
    int gN16  = (n * 16 + T - 1) / T;

    // CSR build
    k_zero<<<gN, T>>>(n);
    k_hist<<<gE, T>>>(dst, nE);
    k_dinv<<<gN, T>>>(n);
    k_scan<<<1, 1024>>>(n);
    k_place<<<gE, T>>>(src, dst, nE);

    // ---- branch 1 ----
    k_gemm<<<gTile, T>>>(x, W1, b1, n, 0, hraw);
    k_gemm<<<gTile, T>>>(x, We, be, n, 1, skip);
    k_agg<0><<<gN16, T>>>(hraw, skip, h, b1, bat, n);
    k_gemm<<<gTile, T>>>(h, W2, b2, n, 0, hraw);
    k_agg<1><<<gN16, T>>>(hraw, h, h, b2, bat, n);

    // ---- branch 2 ----
    k_gemm<<<gTile, T>>>(xsc, W1s, b1s, n, 0, hraw);
    k_gemm<<<gTile, T>>>(xsc, Wes, bes, n, 1, skip);
    k_agg<0><<<gN16, T>>>(hraw, skip, h, b1s, bat, n);
    k_gemm<<<gTile, T>>>(h, W2s, b2s, n, 0, hraw);
    k_agg<1><<<gN16, T>>>(hraw, h, h, b2s, bat, n);

    k_cnt<<<gN, T>>>(bat, n);
    k_final<<<1, 64>>>(Wf, bf, out);
}

// round 6
// speedup vs baseline: 1.4817x; 1.3415x over previous
#include <cuda_runtime.h>
#include <cuda_bf16.h>

#define MAXN 50000
#define MAXE 800000
#define CH   64
#define NG   64
#define SCAN_NB ((MAXN + 1023) / 1024)   // 49

// ---------------- scratch (device globals: no runtime allocation) ----------
__device__ __align__(16) float g_dinv[MAXN];
__device__ __align__(16) float g_selfnorm[MAXN];
__device__ __align__(16) int   g_cnt_i[MAXN];
__device__ __align__(16) int   g_rowptr[MAXN + 1];
__device__ __align__(16) int   g_cursor[MAXN];
__device__ __align__(16) int   g_blocksum[64];
__device__ __align__(16) int   g_blockoff[64];
__device__ __align__(16) int2  g_cedge[MAXE];      // {src, w-as-int-bits}
__device__ __align__(16) float g_hraw[MAXN * CH];
__device__ __align__(16) float g_skip[MAXN * CH];
__device__ __align__(16) float g_h   [MAXN * CH];
__device__ __align__(16) float g_pooled[NG * CH];
__device__ __align__(16) float g_cntf[NG];

// ---------------- build CSR ------------------------------------------------

__global__ void k_zero(int n) {
    int i = blockIdx.x * blockDim.x + threadIdx.x;
    if (i < n)       g_cnt_i[i] = 0;
    if (i < NG * CH) g_pooled[i] = 0.0f;
    if (i < NG)      g_cntf[i] = 0.0f;
}

__global__ void k_hist(const int* __restrict__ dst, int nE) {
    int e = blockIdx.x * blockDim.x + threadIdx.x;
    if (e < nE) atomicAdd(&g_cnt_i[dst[e]], 1);
}

__global__ void k_dinv(int n) {
    int i = blockIdx.x * blockDim.x + threadIdx.x;
    if (i < n) {
        float r = rsqrtf((float)g_cnt_i[i] + 1.0f);   // deg incl. self-loop
        g_dinv[i] = r;
        g_selfnorm[i] = r * r;
    }
}

// ---- parallel exclusive scan of g_cnt_i (3 passes) ----
__global__ void k_scan_p1(int n) {
    __shared__ int sh[1024];
    int i = blockIdx.x * 1024 + threadIdx.x;
    sh[threadIdx.x] = (i < n) ? g_cnt_i[i] : 0;
    __syncthreads();
    #pragma unroll
    for (int s = 512; s > 0; s >>= 1) {
        if (threadIdx.x < s) sh[threadIdx.x] += sh[threadIdx.x + s];
        __syncthreads();
    }
    if (threadIdx.x == 0) g_blocksum[blockIdx.x] = sh[0];
}

__global__ void k_scan_p2(int nB) {
    __shared__ int sh[64];
    int t = threadIdx.x;
    int v = (t < nB) ? g_blocksum[t] : 0;
    sh[t] = v;
    __syncthreads();
    #pragma unroll
    for (int off = 1; off < 64; off <<= 1) {
        int u = (t >= off) ? sh[t - off] : 0;
        __syncthreads();
        sh[t] += u;
        __syncthreads();
    }
    if (t < nB) g_blockoff[t] = sh[t] - v;   // exclusive
}

__global__ void k_scan_p3(int n) {
    __shared__ int sh[1024];
    int i = blockIdx.x * 1024 + threadIdx.x;
    int v = (i < n) ? g_cnt_i[i] : 0;
    sh[threadIdx.x] = v;
    __syncthreads();
    #pragma unroll
    for (int off = 1; off < 1024; off <<= 1) {
        int u = (threadIdx.x >= off) ? sh[threadIdx.x - off] : 0;
        __syncthreads();
        sh[threadIdx.x] += u;
        __syncthreads();
    }
    int ex = g_blockoff[blockIdx.x] + sh[threadIdx.x] - v;
    if (i < n) { g_rowptr[i] = ex; g_cursor[i] = ex; }
    if (i == n - 1) g_rowptr[n] = ex + v;
}

__global__ void k_place(const int* __restrict__ src, const int* __restrict__ dst, int nE) {
    int e = blockIdx.x * blockDim.x + threadIdx.x;
    if (e >= nE) return;
    int s = src[e], d = dst[e];
    int pos = atomicAdd(&g_cursor[d], 1);
    float w = g_dinv[s] * g_dinv[d];
    g_cedge[pos] = make_int2(s, __float_as_int(w));
}

// ---------------- single GEMM: X[n,64] @ W[64,64] --------------------------
// OUT = X@W (raw product, pre-aggregate)
__global__ void k_gemm(const float* __restrict__ X, const float* __restrict__ W,
                       int n, float* __restrict__ OUT)
{
    __shared__ __align__(16) float Ws[64 * 64];
    __shared__ __align__(16) float Xs[64 * 65];

    int tid = threadIdx.x;
    int row0 = blockIdx.x * 64;

    {
        const float4* W4 = (const float4*)W;
        float4* Ws4 = (float4*)Ws;
        for (int i = tid; i < 1024; i += 256) Ws4[i] = W4[i];
    }
    for (int i = tid; i < 1024; i += 256) {
        int r  = i >> 4;
        int c4 = (i & 15) << 2;
        int gr = row0 + r;
        float4 v = make_float4(0.f, 0.f, 0.f, 0.f);
        if (gr < n) v = *(const float4*)(X + gr * 64 + c4);
        float* p = &Xs[r * 65 + c4];
        p[0] = v.x; p[1] = v.y; p[2] = v.z; p[3] = v.w;
    }
    __syncthreads();

    int tx = tid & 15;
    int ty = tid >> 4;

    float a00=0,a01=0,a02=0,a03=0, a10=0,a11=0,a12=0,a13=0;
    float a20=0,a21=0,a22=0,a23=0, a30=0,a31=0,a32=0,a33=0;

    #pragma unroll
    for (int k = 0; k < 64; k++) {
        float4 w = *(const float4*)&Ws[k * 64 + tx * 4];
        float x0 = Xs[(ty * 4 + 0) * 65 + k];
        float x1 = Xs[(ty * 4 + 1) * 65 + k];
        float x2 = Xs[(ty * 4 + 2) * 65 + k];
        float x3 = Xs[(ty * 4 + 3) * 65 + k];
        a00 = fmaf(x0, w.x, a00); a01 = fmaf(x0, w.y, a01);
        a02 = fmaf(x0, w.z, a02); a03 = fmaf(x0, w.w, a03);
        a10 = fmaf(x1, w.x, a10); a11 = fmaf(x1, w.y, a11);
        a12 = fmaf(x1, w.z, a12); a13 = fmaf(x1, w.w, a13);
        a20 = fmaf(x2, w.x, a20); a21 = fmaf(x2, w.y, a21);
        a22 = fmaf(x2, w.z, a22); a23 = fmaf(x2, w.w, a23);
        a30 = fmaf(x3, w.x, a30); a31 = fmaf(x3, w.y, a31);
        a32 = fmaf(x3, w.z, a32); a33 = fmaf(x3, w.w, a33);
    }

    int c0 = tx * 4;
    float rows[4][4] = {{a00,a01,a02,a03},{a10,a11,a12,a13},
                        {a20,a21,a22,a23},{a30,a31,a32,a33}};
    #pragma unroll
    for (int i = 0; i < 4; i++) {
        int r = row0 + ty * 4 + i;
        if (r >= n) break;
        *(float4*)(OUT + r * 64 + c0) =
            make_float4(rows[i][0], rows[i][1], rows[i][2], rows[i][3]);
    }
}

// ---------------- dual GEMM: OUTa = X@Wa (raw), OUTb = relu(X@Wb + bb) -----
// Shares the X tile between both products (layer-1 GCN + dense skip).
__global__ void k_gemm2(const float* __restrict__ X,
                        const float* __restrict__ Wa,
                        const float* __restrict__ Wb, const float* __restrict__ bb,
                        int n, float* __restrict__ OUTa, float* __restrict__ OUTb)
{
    __shared__ __align__(16) float Wsa[64 * 64];
    __shared__ __align__(16) float Wsb[64 * 64];
    __shared__ __align__(16) float Xs[64 * 65];

    int tid = threadIdx.x;
    int row0 = blockIdx.x * 64;

    {
        const float4* Wa4 = (const float4*)Wa;
        const float4* Wb4 = (const float4*)Wb;
        float4* a4 = (float4*)Wsa;
        float4* b4 = (float4*)Wsb;
        for (int i = tid; i < 1024; i += 256) { a4[i] = Wa4[i]; b4[i] = Wb4[i]; }
    }
    for (int i = tid; i < 1024; i += 256) {
        int r  = i >> 4;
        int c4 = (i & 15) << 2;
        int gr = row0 + r;
        float4 v = make_float4(0.f, 0.f, 0.f, 0.f);
        if (gr < n) v = *(const float4*)(X + gr * 64 + c4);
        float* p = &Xs[r * 65 + c4];
        p[0] = v.x; p[1] = v.y; p[2] = v.z; p[3] = v.w;
    }
    __syncthreads();

    int tx = tid & 15;
    int ty = tid >> 4;

    float A[4][4] = {}, B[4][4] = {};

    #pragma unroll
    for (int k = 0; k < 64; k++) {
        float4 wa = *(const float4*)&Wsa[k * 64 + tx * 4];
        float4 wb = *(const float4*)&Wsb[k * 64 + tx * 4];
        float xr[4];
        #pragma unroll
        for (int i = 0; i < 4; i++) xr[i] = Xs[(ty * 4 + i) * 65 + k];
        #pragma unroll
        for (int i = 0; i < 4; i++) {
            A[i][0] = fmaf(xr[i], wa.x, A[i][0]);
            A[i][1] = fmaf(xr[i], wa.y, A[i][1]);
            A[i][2] = fmaf(xr[i], wa.z, A[i][2]);
            A[i][3] = fmaf(xr[i], wa.w, A[i][3]);
            B[i][0] = fmaf(xr[i], wb.x, B[i][0]);
            B[i][1] = fmaf(xr[i], wb.y, B[i][1]);
            B[i][2] = fmaf(xr[i], wb.z, B[i][2]);
            B[i][3] = fmaf(xr[i], wb.w, B[i][3]);
        }
    }

    int c0 = tx * 4;
    float4 bv = *(const float4*)(bb + c0);
    #pragma unroll
    for (int i = 0; i < 4; i++) {
        int r = row0 + ty * 4 + i;
        if (r >= n) break;
        *(float4*)(OUTa + r * 64 + c0) = make_float4(A[i][0], A[i][1], A[i][2], A[i][3]);
        *(float4*)(OUTb + r * 64 + c0) =
            make_float4(fmaxf(B[i][0] + bv.x, 0.f), fmaxf(B[i][1] + bv.y, 0.f),
                        fmaxf(B[i][2] + bv.z, 0.f), fmaxf(B[i][3] + bv.w, 0.f));
    }
}

// ---------------- fused GCN aggregate --------------------------------------
// OUT[d] = relu( sum_{e in CSR(d)} w_e * H[src_e] + selfnorm[d]*H[d] + b ) + SKIP[d]
// if DO_POOL: red-add OUT row into g_pooled[batch[d]]
template<int DO_POOL>
__global__ void k_agg(const float* __restrict__ H, const float* __restrict__ SKIP,
                      float* __restrict__ OUT, const float* __restrict__ b,
                      const int* __restrict__ batch, int n)
{
    int t = blockIdx.x * blockDim.x + threadIdx.x;
    int node = t >> 4;
    if (node >= n) return;
    int c4 = (t & 15) << 2;

    int beg = g_rowptr[node];
    int end = g_rowptr[node + 1];

    float sn = g_selfnorm[node];
    float4 hd = *(const float4*)(H + node * 64 + c4);
    float4 acc = make_float4(sn * hd.x, sn * hd.y, sn * hd.z, sn * hd.w);

    for (int j = beg; j < end; j++) {
        int2 e = __ldg(&g_cedge[j]);
        float w = __int_as_float(e.y);
        float4 hv = *(const float4*)(H + e.x * 64 + c4);
        acc.x = fmaf(w, hv.x, acc.x);
        acc.y = fmaf(w, hv.y, acc.y);
        acc.z = fmaf(w, hv.z, acc.z);
        acc.w = fmaf(w, hv.w, acc.w);
    }

    float4 bv = *(const float4*)(b + c4);
    float4 sk = *(const float4*)(SKIP + node * 64 + c4);
    float4 o = make_float4(fmaxf(acc.x + bv.x, 0.f) + sk.x,
                           fmaxf(acc.y + bv.y, 0.f) + sk.y,
                           fmaxf(acc.z + bv.z, 0.f) + sk.z,
                           fmaxf(acc.w + bv.w, 0.f) + sk.w);
    *(float4*)(OUT + node * 64 + c4) = o;

    if (DO_POOL) {
        int g = batch[node];
        float* p = g_pooled + g * 64 + c4;
        asm volatile("red.global.add.v4.f32 [%0], {%1,%2,%3,%4};"
                     :: "l"(p), "f"(o.x), "f"(o.y), "f"(o.z), "f"(o.w)
                     : "memory");
    }
}

__global__ void k_cnt(const int* __restrict__ batch, int n) {
    int i = blockIdx.x * blockDim.x + threadIdx.x;
    if (i < n) atomicAdd(&g_cntf[batch[i]], 1.0f);
}

__global__ void k_final(const float* __restrict__ Wf, const float* __restrict__ bf,
                        float* __restrict__ out)
{
    int g = threadIdx.x;
    if (g >= NG) return;
    float cnt = fmaxf(g_cntf[g], 1.0f);
    float acc = 0.f;
    #pragma unroll
    for (int c = 0; c < CH; c++) acc += g_pooled[g * CH + c] * Wf[c];
    out[g] = acc / cnt + bf[0];
}

// ---------------- host -----------------------------------------------------

extern "C" void kernel_launch(void* const* d_in, const int* in_sizes, int n_in,
                              void* d_out, int out_size)
{
    const float* x   = (const float*)d_in[0];
    const float* xsc = (const float*)d_in[1];
    const float* W1  = (const float*)d_in[2];
    const float* b1  = (const float*)d_in[3];
    const float* W2  = (const float*)d_in[4];
    const float* b2  = (const float*)d_in[5];
    const float* We  = (const float*)d_in[6];
    const float* be  = (const float*)d_in[7];
    const float* W1s = (const float*)d_in[8];
    const float* b1s = (const float*)d_in[9];
    const float* W2s = (const float*)d_in[10];
    const float* b2s = (const float*)d_in[11];
    const float* Wes = (const float*)d_in[12];
    const float* bes = (const float*)d_in[13];
    const float* Wf  = (const float*)d_in[14];
    const float* bf  = (const float*)d_in[15];
    const int*   ei  = (const int*)d_in[16];
    const int*   bat = (const int*)d_in[17];

    int n  = in_sizes[0] / CH;
    int nE = in_sizes[16] / 2;
    const int* src = ei;
    const int* dst = ei + nE;
    float* out = (float*)d_out;

    float *hraw, *skip, *h;
    cudaGetSymbolAddress((void**)&hraw, g_hraw);
    cudaGetSymbolAddress((void**)&skip, g_skip);
    cudaGetSymbolAddress((void**)&h,    g_h);

    const int T = 256;
    int gN    = (n + T - 1) / T;
    int gE    = (nE + T - 1) / T;
    int gTile = (n + 63) / 64;
    int gN16  = (n * 16 + T - 1) / T;
    int nB    = (n + 1023) / 1024;

    // CSR build
    k_zero<<<gN, T>>>(n);
    k_hist<<<gE, T>>>(dst, nE);
    k_dinv<<<gN, T>>>(n);
    k_scan_p1<<<nB, 1024>>>(n);
    k_scan_p2<<<1, 64>>>(nB);
    k_scan_p3<<<nB, 1024>>>(n);
    k_place<<<gE, T>>>(src, dst, nE);

    // ---- branch 1 ----
    k_gemm2<<<gTile, T>>>(x, W1, We, be, n, hraw, skip);
    k_agg<0><<<gN16, T>>>(hraw, skip, h, b1, bat, n);
    k_gemm<<<gTile, T>>>(h, W2, n, hraw);
    k_agg<1><<<gN16, T>>>(hraw, h, h, b2, bat, n);

    // ---- branch 2 ----
    k_gemm2<<<gTile, T>>>(xsc, W1s, Wes, bes, n, hraw, skip);
    k_agg<0><<<gN16, T>>>(hraw, skip, h, b1s, bat, n);
    k_gemm<<<gTile, T>>>(h, W2s, n, hraw);
    k_agg<1><<<gN16, T>>>(hraw, h, h, b2s, bat, n);

    k_cnt<<<gN, T>>>(bat, n);
    k_final<<<1, 64>>>(Wf, bf, out);
}